// round 1
// baseline (speedup 1.0000x reference)
#include <cuda_runtime.h>
#include <cuda_bf16.h>
#include <cstdint>

// Problem constants
#define BATCH   4096
#define IN_DIM  2048
#define HID     2048
#define LD      2048      // leading dim of X, S, W_psp, W_rec (all 2048)

#define BM 128
#define BN 128
#define BK 16
#define TM 8
#define TN 8
#define NTHREADS 256

#define KT1 (IN_DIM / BK)                 // 128 tiles for X @ W_psp
#define NT  ((IN_DIM + HID) / BK)         // 256 total K tiles

__global__ __launch_bounds__(NTHREADS, 2)
void lif_fused_kernel(const float* __restrict__ X,      // [B, IN_DIM]
                      const float* __restrict__ S,      // [B, HID] pre_spike
                      const float* __restrict__ preC,   // [B, HID]
                      const float* __restrict__ preV,   // [B, HID]
                      const float* __restrict__ preTh,  // [B, HID]
                      const float* __restrict__ mask,   // [B, HID]
                      const float* __restrict__ Wpsp,   // [IN_DIM, HID]
                      const float* __restrict__ bpsp,   // [HID]
                      const float* __restrict__ Wrec,   // [HID, HID]
                      const float* __restrict__ brec,   // [HID]
                      float* __restrict__ out,
                      int sections)
{
    __shared__ float As[2][BK][BM];
    __shared__ float Bs[2][BK][BN];

    const int tid = threadIdx.x;
    const int tx = tid & 15;          // n-dim thread coord (0..15)
    const int ty = tid >> 4;          // m-dim thread coord (0..15)

    const int m0 = blockIdx.y * BM;
    const int n0 = blockIdx.x * BN;

    // Loader coordinates
    const int arow = tid >> 2;        // 0..63   (A tile rows, two halves)
    const int acol = (tid & 3) * 4;   // 0,4,8,12 (A tile k-cols, float4 group)
    const int brow = tid >> 4;        // 0..15   (B tile k-rows)
    const int bcol = (tid & 15) * 4;  // 0..60   (B tile n-cols, two halves)

    float acc[TM][TN];
    #pragma unroll
    for (int i = 0; i < TM; i++)
        #pragma unroll
        for (int j = 0; j < TN; j++) acc[i][j] = 0.0f;

    // ---- Prologue: load tile 0 (X / Wpsp, k0 = 0) into buffer 0 ----
    {
        const float* Ap = X;
        const float* Bp = Wpsp;
        float4 a0 = *(const float4*)&Ap[(size_t)(m0 + arow) * LD + acol];
        float4 a1 = *(const float4*)&Ap[(size_t)(m0 + arow + 64) * LD + acol];
        float4 b0 = *(const float4*)&Bp[(size_t)brow * LD + n0 + bcol];
        float4 b1 = *(const float4*)&Bp[(size_t)brow * LD + n0 + bcol + 64];
        As[0][acol + 0][arow] = a0.x;  As[0][acol + 1][arow] = a0.y;
        As[0][acol + 2][arow] = a0.z;  As[0][acol + 3][arow] = a0.w;
        As[0][acol + 0][arow + 64] = a1.x;  As[0][acol + 1][arow + 64] = a1.y;
        As[0][acol + 2][arow + 64] = a1.z;  As[0][acol + 3][arow + 64] = a1.w;
        *(float4*)&Bs[0][brow][bcol]      = b0;
        *(float4*)&Bs[0][brow][bcol + 64] = b1;
    }
    __syncthreads();

    // ---- Main loop over 256 K-tiles (first 128: X@Wpsp, next 128: S@Wrec) ----
    for (int t = 0; t < NT; ++t) {
        const int cur = t & 1;
        const int nxt = cur ^ 1;
        float4 a0, a1, b0, b1;
        const bool hasNext = (t + 1 < NT);

        if (hasNext) {
            const int tn = t + 1;
            const float* Ap;
            const float* Bp;
            int k0;
            if (tn < KT1) { Ap = X; Bp = Wpsp; k0 = tn * BK; }
            else          { Ap = S; Bp = Wrec; k0 = (tn - KT1) * BK; }
            a0 = *(const float4*)&Ap[(size_t)(m0 + arow) * LD + k0 + acol];
            a1 = *(const float4*)&Ap[(size_t)(m0 + arow + 64) * LD + k0 + acol];
            b0 = *(const float4*)&Bp[(size_t)(k0 + brow) * LD + n0 + bcol];
            b1 = *(const float4*)&Bp[(size_t)(k0 + brow) * LD + n0 + bcol + 64];
        }

        // Compute on current buffer
        #pragma unroll
        for (int kk = 0; kk < BK; ++kk) {
            float ra[TM], rb[TN];
            *(float4*)&ra[0] = *(const float4*)&As[cur][kk][ty * TM];
            *(float4*)&ra[4] = *(const float4*)&As[cur][kk][ty * TM + 4];
            *(float4*)&rb[0] = *(const float4*)&Bs[cur][kk][tx * TN];
            *(float4*)&rb[4] = *(const float4*)&Bs[cur][kk][tx * TN + 4];
            #pragma unroll
            for (int i = 0; i < TM; i++)
                #pragma unroll
                for (int j = 0; j < TN; j++)
                    acc[i][j] = fmaf(ra[i], rb[j], acc[i][j]);
        }

        if (hasNext) {
            As[nxt][acol + 0][arow] = a0.x;  As[nxt][acol + 1][arow] = a0.y;
            As[nxt][acol + 2][arow] = a0.z;  As[nxt][acol + 3][arow] = a0.w;
            As[nxt][acol + 0][arow + 64] = a1.x;  As[nxt][acol + 1][arow + 64] = a1.y;
            As[nxt][acol + 2][arow + 64] = a1.z;  As[nxt][acol + 3][arow + 64] = a1.w;
            *(float4*)&Bs[nxt][brow][bcol]      = b0;
            *(float4*)&Bs[nxt][brow][bcol + 64] = b1;
        }
        __syncthreads();
    }

    // ---- Fused LIF epilogue ----
    // current = 0.5*preC + gemm + bpsp + brec;  current *= mask
    // volt    = 0.75*preV*(1-preS) + current
    // spike   = volt > preTh
    // vth     = spike ? preTh+0.05 : max(preTh*0.9, 1.0)
    // out layout (pytree flatten): [spike, spike, current, volt, vth]
    const size_t NE = (size_t)BATCH * HID;

    #pragma unroll
    for (int i = 0; i < TM; i++) {
        const int m = m0 + ty * TM + i;
        const size_t rowoff = (size_t)m * HID;
        #pragma unroll
        for (int g = 0; g < 2; g++) {
            const int n = n0 + tx * TN + g * 4;
            const size_t idx = rowoff + n;

            float pc[4], pv[4], ps[4], pth[4], mk[4], b1[4], b2[4];
            *(float4*)pc  = *(const float4*)&preC[idx];
            *(float4*)pv  = *(const float4*)&preV[idx];
            *(float4*)ps  = *(const float4*)&S[idx];
            *(float4*)pth = *(const float4*)&preTh[idx];
            *(float4*)mk  = *(const float4*)&mask[idx];
            *(float4*)b1  = *(const float4*)&bpsp[n];
            *(float4*)b2  = *(const float4*)&brec[n];

            float sp[4], cu[4], vo[4], th[4];
            #pragma unroll
            for (int j = 0; j < 4; j++) {
                float c = fmaf(0.5f, pc[j], acc[i][g * 4 + j] + b1[j] + b2[j]);
                c *= mk[j];
                float v = fmaf(0.75f * pv[j], (1.0f - ps[j]), c);
                float s = (v > pth[j]) ? 1.0f : 0.0f;
                float t = (s != 0.0f) ? (pth[j] + 0.05f)
                                      : fmaxf(pth[j] * 0.9f, 1.0f);
                cu[j] = c; vo[j] = v; sp[j] = s; th[j] = t;
            }

            *(float4*)&out[idx] = *(float4*)sp;
            if (sections > 1) *(float4*)&out[NE + idx]     = *(float4*)sp;
            if (sections > 2) *(float4*)&out[2 * NE + idx] = *(float4*)cu;
            if (sections > 3) *(float4*)&out[3 * NE + idx] = *(float4*)vo;
            if (sections > 4) *(float4*)&out[4 * NE + idx] = *(float4*)th;
        }
    }
}

extern "C" void kernel_launch(void* const* d_in, const int* in_sizes, int n_in,
                              void* d_out, int out_size) {
    const float* X     = (const float*)d_in[0];  // input_data [B, IN_DIM]
    const float* S     = (const float*)d_in[1];  // pre_spike  [B, HID]
    const float* preC  = (const float*)d_in[2];  // pre_current
    const float* preV  = (const float*)d_in[3];  // pre_volt
    const float* preTh = (const float*)d_in[4];  // pre_vth
    const float* mk    = (const float*)d_in[5];  // mask
    const float* Wpsp  = (const float*)d_in[6];  // [IN_DIM, HID]
    const float* bpsp  = (const float*)d_in[7];  // [HID]
    const float* Wrec  = (const float*)d_in[8];  // [HID, HID]
    const float* brec  = (const float*)d_in[9];  // [HID]

    const long long NE = (long long)BATCH * HID;
    int sections = (int)((long long)out_size / NE);
    if (sections < 1) sections = 1;
    if (sections > 5) sections = 5;

    dim3 grid(HID / BN, BATCH / BM);   // (16, 32) = 512 CTAs
    lif_fused_kernel<<<grid, NTHREADS>>>(X, S, preC, preV, preTh, mk,
                                         Wpsp, bpsp, Wrec, brec,
                                         (float*)d_out, sections);
}

// round 5
// speedup vs baseline: 1.6256x; 1.6256x over previous
#include <cuda_runtime.h>
#include <cuda_bf16.h>
#include <cstdint>

#define BATCH  4096
#define INDIM  2048
#define HIDDEN 2048

#define BM 128
#define BN 128
#define BK 16
#define NST1 (INDIM / BK)               // 128 stages: X@Wpsp
#define NST  ((INDIM + HIDDEN) / BK)    // 256 total

// per-stage smem byte offsets (rows padded to 48B stride -> conflict-free ldmatrix)
#define TILE_B  6144                    // 128 rows * 48B
#define OFF_A0  0
#define OFF_A1  6144
#define OFF_B0  12288
#define OFF_B1  18432
#define STAGE_B 24576
#define SMEM_BYTES (3 * STAGE_B)        // 73728, 3-stage pipeline

#define DELTA    0.01f
#define LIST_CAP (1u << 21)

// ---------------- device scratch ----------------
__device__ __nv_bfloat16 g_X0[(size_t)BATCH * INDIM];
__device__ __nv_bfloat16 g_X1[(size_t)BATCH * INDIM];
__device__ __nv_bfloat16 g_Sb[(size_t)BATCH * HIDDEN];
__device__ __nv_bfloat16 g_P0T[(size_t)HIDDEN * INDIM];   // Wpsp^T limb0 [n][k]
__device__ __nv_bfloat16 g_P1T[(size_t)HIDDEN * INDIM];
__device__ float         g_PfT[(size_t)HIDDEN * INDIM];   // Wpsp^T exact fp32
__device__ __nv_bfloat16 g_R0T[(size_t)HIDDEN * HIDDEN];
__device__ __nv_bfloat16 g_R1T[(size_t)HIDDEN * HIDDEN];
__device__ float         g_RfT[(size_t)HIDDEN * HIDDEN];
__device__ uint32_t      g_count;
__device__ uint32_t      g_list[LIST_CAP];

// ---------------- helpers ----------------
__device__ __forceinline__ uint32_t s2u(const void* p) {
    uint32_t a;
    asm("{ .reg .u64 t; cvta.to.shared.u64 t, %1; cvt.u32.u64 %0, t; }"
        : "=r"(a) : "l"(p));
    return a;
}
__device__ __forceinline__ void split2(float v, __nv_bfloat16& b0, __nv_bfloat16& b1) {
    b0 = __float2bfloat16_rn(v);
    b1 = __float2bfloat16_rn(v - __bfloat162float(b0));
}
__device__ __forceinline__ void cp16(uint32_t d, const void* s) {
    asm volatile("cp.async.cg.shared.global [%0], [%1], 16;" :: "r"(d), "l"(s));
}
__device__ __forceinline__ void ldm4(uint32_t* r, uint32_t addr) {
    asm volatile("ldmatrix.sync.aligned.m8n8.x4.shared.b16 {%0,%1,%2,%3}, [%4];"
                 : "=r"(r[0]), "=r"(r[1]), "=r"(r[2]), "=r"(r[3]) : "r"(addr));
}
__device__ __forceinline__ void mma16(float* d, const uint32_t* a, const uint32_t* b) {
    asm volatile(
        "mma.sync.aligned.m16n8k16.row.col.f32.bf16.bf16.f32 "
        "{%0,%1,%2,%3},{%4,%5,%6,%7},{%8,%9},{%0,%1,%2,%3};"
        : "+f"(d[0]), "+f"(d[1]), "+f"(d[2]), "+f"(d[3])
        : "r"(a[0]), "r"(a[1]), "r"(a[2]), "r"(a[3]), "r"(b[0]), "r"(b[1]));
}

// ---------------- pre-kernels ----------------
__global__ void split_x_k(const float2* __restrict__ src, size_t n2) {
    size_t i = (size_t)blockIdx.x * blockDim.x + threadIdx.x;
    if (i == 0) g_count = 0;                        // reset fixup list
    if (i >= n2) return;
    float2 v = src[i];
    __nv_bfloat16 a0, a1, b0, b1;
    split2(v.x, a0, a1);
    split2(v.y, b0, b1);
    ((__nv_bfloat162*)g_X0)[i] = __nv_bfloat162(a0, b0);
    ((__nv_bfloat162*)g_X1)[i] = __nv_bfloat162(a1, b1);
}
__global__ void conv_s_k(const float2* __restrict__ src, size_t n2) {
    size_t i = (size_t)blockIdx.x * blockDim.x + threadIdx.x;
    if (i >= n2) return;
    float2 v = src[i];
    ((__nv_bfloat162*)g_Sb)[i] =
        __nv_bfloat162(__float2bfloat16_rn(v.x), __float2bfloat16_rn(v.y));
}
__global__ void split_wT_k(const float* __restrict__ W, int which) {
    __shared__ float tile[32][33];
    __nv_bfloat16* o0 = which ? g_R0T : g_P0T;
    __nv_bfloat16* o1 = which ? g_R1T : g_P1T;
    float*         of = which ? g_RfT : g_PfT;
    const int n0 = blockIdx.x * 32, k0 = blockIdx.y * 32;
    const int tx = threadIdx.x, ty = threadIdx.y;
    #pragma unroll
    for (int r = ty; r < 32; r += 8)
        tile[r][tx] = W[(size_t)(k0 + r) * HIDDEN + n0 + tx];
    __syncthreads();
    #pragma unroll
    for (int r = ty; r < 32; r += 8) {
        float v = tile[tx][r];                 // = W[k0+tx][n0+r]
        __nv_bfloat16 b0, b1;
        split2(v, b0, b1);
        size_t o = (size_t)(n0 + r) * INDIM + k0 + tx;   // [n][k]
        o0[o] = b0; o1[o] = b1; of[o] = v;
    }
}

// ---------------- main fused GEMM + LIF + band detect ----------------
__global__ void __launch_bounds__(256, 1)
gemm_lif(const float* __restrict__ S, const float* __restrict__ preC,
         const float* __restrict__ preV, const float* __restrict__ preTh,
         const float* __restrict__ mask, const float* __restrict__ bpsp,
         const float* __restrict__ brec, float* __restrict__ out, int sections)
{
    extern __shared__ char smem[];
    const uint32_t sb = s2u(smem);
    const int tid = threadIdx.x;
    const int lane = tid & 31, warp = tid >> 5;
    const int g = lane >> 2, t4 = lane & 3;
    const int wm = warp >> 2, wn = warp & 3;           // 2 x 4 warps
    const int m0 = blockIdx.y * BM, n0 = blockIdx.x * BN;

    const uint32_t aoff =
        (uint32_t)((((lane & 7) + ((lane >> 3) & 1) * 8) * 48) + (lane >> 4) * 16);
    const uint32_t boff =
        (uint32_t)((((lane & 7) + ((lane >> 4) & 1) * 8) * 48) + ((lane >> 3) & 1) * 16);

    float acc[4][4][4];
    #pragma unroll
    for (int i = 0; i < 4; i++)
        #pragma unroll
        for (int j = 0; j < 4; j++)
            #pragma unroll
            for (int q = 0; q < 4; q++) acc[i][j][q] = 0.0f;

    // stage loader: 4 cp.async per thread (one 16B chunk per tile)
    const int lr = tid >> 1, lc = tid & 1;
    const uint32_t ldst = (uint32_t)(lr * 48 + lc * 16);
    auto load_stage = [&](int t) {
        const uint32_t base = sb + (uint32_t)((t % 3) * STAGE_B);
        const size_t ae = (size_t)(m0 + lr) * 2048 + lc * 8;
        const size_t be = (size_t)(n0 + lr) * 2048 + lc * 8;
        if (t < NST1) {
            const int k0 = t * BK;
            cp16(base + OFF_A0 + ldst, g_X0 + ae + k0);
            cp16(base + OFF_A1 + ldst, g_X1 + ae + k0);
            cp16(base + OFF_B0 + ldst, g_P0T + be + k0);
            cp16(base + OFF_B1 + ldst, g_P1T + be + k0);
        } else {
            const int k0 = (t - NST1) * BK;
            cp16(base + OFF_A0 + ldst, g_Sb + ae + k0);
            cp16(base + OFF_B0 + ldst, g_R0T + be + k0);
            cp16(base + OFF_B1 + ldst, g_R1T + be + k0);
        }
    };

    uint32_t fa[4][4], fb0[4][2], fb1[4][2];
    auto ldA = [&](uint32_t tbase) {
        #pragma unroll
        for (int mf = 0; mf < 4; mf++)
            ldm4(fa[mf], tbase + (uint32_t)((wm * 64 + mf * 16) * 48) + aoff);
    };
    auto ldB = [&](uint32_t tbase, uint32_t (*fb)[2]) {
        #pragma unroll
        for (int p = 0; p < 2; p++) {
            uint32_t r[4];
            ldm4(r, tbase + (uint32_t)((wn * 32 + p * 16) * 48) + boff);
            fb[2 * p][0] = r[0]; fb[2 * p][1] = r[1];
            fb[2 * p + 1][0] = r[2]; fb[2 * p + 1][1] = r[3];
        }
    };
    auto mma_all = [&](uint32_t (*fb)[2]) {
        #pragma unroll
        for (int mf = 0; mf < 4; mf++)
            #pragma unroll
            for (int nf = 0; nf < 4; nf++)
                mma16(acc[mf][nf], fa[mf], fb[nf]);
    };

    load_stage(0);
    asm volatile("cp.async.commit_group;" ::: "memory");
    load_stage(1);
    asm volatile("cp.async.commit_group;" ::: "memory");

    for (int t = 0; t < NST; ++t) {
        if (t + 1 < NST)
            asm volatile("cp.async.wait_group 1;" ::: "memory");
        else
            asm volatile("cp.async.wait_group 0;" ::: "memory");
        __syncthreads();

        if (t + 2 < NST) {
            load_stage(t + 2);
            asm volatile("cp.async.commit_group;" ::: "memory");
        }

        const uint32_t stb = sb + (uint32_t)((t % 3) * STAGE_B);
        if (t < NST1) {
            ldA(stb + OFF_A0);
            ldB(stb + OFF_B0, fb0);
            ldB(stb + OFF_B1, fb1);
            mma_all(fb0);
            mma_all(fb1);
            ldA(stb + OFF_A1);
            mma_all(fb0);
        } else {
            ldA(stb + OFF_A0);
            ldB(stb + OFF_B0, fb0);
            ldB(stb + OFF_B1, fb1);
            mma_all(fb0);
            mma_all(fb1);
        }
    }

    // ---------------- fused LIF epilogue + band detection ----------------
    const size_t NE = (size_t)BATCH * HIDDEN;
    #pragma unroll
    for (int mf = 0; mf < 4; mf++) {
        #pragma unroll
        for (int rh = 0; rh < 2; rh++) {
            const int m = m0 + wm * 64 + mf * 16 + g + rh * 8;
            const size_t row = (size_t)m * HIDDEN;
            #pragma unroll
            for (int nf = 0; nf < 4; nf++) {
                const int n = n0 + wn * 32 + nf * 8 + 2 * t4;
                const size_t idx = row + n;
                float2 pc = *(const float2*)(preC  + idx);
                float2 pv = *(const float2*)(preV  + idx);
                float2 ps = *(const float2*)(S     + idx);
                float2 pt = *(const float2*)(preTh + idx);
                float2 mk = *(const float2*)(mask  + idx);
                float2 b1 = *(const float2*)(bpsp  + n);
                float2 b2 = *(const float2*)(brec  + n);

                float av[2]  = { acc[mf][nf][rh * 2 + 0], acc[mf][nf][rh * 2 + 1] };
                float pcv[2] = { pc.x, pc.y }, pvv[2] = { pv.x, pv.y };
                float psv[2] = { ps.x, ps.y }, ptv[2] = { pt.x, pt.y };
                float mkv[2] = { mk.x, mk.y };
                float b1v[2] = { b1.x, b1.y }, b2v[2] = { b2.x, b2.y };

                float sp[2], cu[2], vo[2], th[2];
                #pragma unroll
                for (int q = 0; q < 2; q++) {
                    float c = fmaf(0.5f, pcv[q], av[q] + b1v[q] + b2v[q]);
                    c *= mkv[q];
                    float v = fmaf(0.75f * pvv[q], (1.0f - psv[q]), c);
                    float s = (v > ptv[q]) ? 1.0f : 0.0f;
                    float tv = (s != 0.0f) ? (ptv[q] + 0.05f)
                                           : fmaxf(ptv[q] * 0.9f, 1.0f);
                    sp[q] = s; cu[q] = c; vo[q] = v; th[q] = tv;
                    if (fabsf(v - ptv[q]) < DELTA) {
                        uint32_t pos = atomicAdd(&g_count, 1u);
                        if (pos < LIST_CAP)
                            g_list[pos] = (uint32_t)((m << 11) | (n + q));
                    }
                }
                *(float2*)(out + idx) = make_float2(sp[0], sp[1]);
                if (sections > 1) *(float2*)(out + NE + idx)     = make_float2(sp[0], sp[1]);
                if (sections > 2) *(float2*)(out + 2 * NE + idx) = make_float2(cu[0], cu[1]);
                if (sections > 3) *(float2*)(out + 3 * NE + idx) = make_float2(vo[0], vo[1]);
                if (sections > 4) *(float2*)(out + 4 * NE + idx) = make_float2(th[0], th[1]);
            }
        }
    }
}

// ---------------- exact fp32 fixup of near-threshold elements ----------------
__global__ void fixup_k(const float* __restrict__ X, const float* __restrict__ S,
                        const float* __restrict__ preC, const float* __restrict__ preV,
                        const float* __restrict__ preTh, const float* __restrict__ mask,
                        const float* __restrict__ bpsp, const float* __restrict__ brec,
                        float* __restrict__ out, int sections)
{
    const int lane = threadIdx.x & 31;
    const uint32_t wglob = (blockIdx.x * blockDim.x + threadIdx.x) >> 5;
    const uint32_t nw = (gridDim.x * blockDim.x) >> 5;
    uint32_t cnt = g_count;
    if (cnt > LIST_CAP) cnt = LIST_CAP;
    const size_t NE = (size_t)BATCH * HIDDEN;

    for (uint32_t i = wglob; i < cnt; i += nw) {
        const uint32_t e = g_list[i];
        const int m = (int)(e >> 11), n = (int)(e & 2047);
        const float* xr = X + (size_t)m * INDIM;
        const float* wr = g_PfT + (size_t)n * INDIM;
        const float* sr = S + (size_t)m * HIDDEN;
        const float* rr = g_RfT + (size_t)n * HIDDEN;
        float a = 0.0f;
        #pragma unroll 4
        for (int k = lane; k < INDIM; k += 32) a = fmaf(xr[k], wr[k], a);
        #pragma unroll 4
        for (int k = lane; k < HIDDEN; k += 32) a = fmaf(sr[k], rr[k], a);
        #pragma unroll
        for (int o = 16; o; o >>= 1) a += __shfl_xor_sync(0xFFFFFFFFu, a, o);

        if (lane == 0) {
            const size_t idx = (size_t)m * HIDDEN + n;
            float c = fmaf(0.5f, preC[idx], a + bpsp[n] + brec[n]);
            c *= mask[idx];
            float v = fmaf(0.75f * preV[idx], (1.0f - S[idx]), c);
            float pt = preTh[idx];
            float sp = (v > pt) ? 1.0f : 0.0f;
            float tv = (sp != 0.0f) ? (pt + 0.05f) : fmaxf(pt * 0.9f, 1.0f);
            out[idx] = sp;
            if (sections > 1) out[NE + idx]     = sp;
            if (sections > 2) out[2 * NE + idx] = c;
            if (sections > 3) out[3 * NE + idx] = v;
            if (sections > 4) out[4 * NE + idx] = tv;
        }
    }
}

// ---------------- launch ----------------
extern "C" void kernel_launch(void* const* d_in, const int* in_sizes, int n_in,
                              void* d_out, int out_size) {
    const float* X     = (const float*)d_in[0];
    const float* S     = (const float*)d_in[1];
    const float* preC  = (const float*)d_in[2];
    const float* preV  = (const float*)d_in[3];
    const float* preTh = (const float*)d_in[4];
    const float* mk    = (const float*)d_in[5];
    const float* Wpsp  = (const float*)d_in[6];
    const float* bpsp  = (const float*)d_in[7];
    const float* Wrec  = (const float*)d_in[8];
    const float* brec  = (const float*)d_in[9];

    const long long NE = (long long)BATCH * HIDDEN;
    int sections = (int)((long long)out_size / NE);
    if (sections < 1) sections = 1;
    if (sections > 5) sections = 5;

    cudaFuncSetAttribute(gemm_lif, cudaFuncAttributeMaxDynamicSharedMemorySize,
                         SMEM_BYTES);

    const size_t n2x = (size_t)BATCH * INDIM / 2;
    split_x_k<<<(unsigned)((n2x + 255) / 256), 256>>>((const float2*)X, n2x);
    conv_s_k<<<(unsigned)((n2x + 255) / 256), 256>>>((const float2*)S, n2x);
    dim3 wg(HIDDEN / 32, INDIM / 32), wb(32, 8);
    split_wT_k<<<wg, wb>>>(Wpsp, 0);
    split_wT_k<<<wg, wb>>>(Wrec, 1);

    dim3 grid(HIDDEN / BN, BATCH / BM);   // (16, 32) = 512 CTAs
    gemm_lif<<<grid, 256, SMEM_BYTES>>>(S, preC, preV, preTh, mk, bpsp, brec,
                                        (float*)d_out, sections);
    fixup_k<<<256, 256>>>(X, S, preC, preV, preTh, mk, bpsp, brec,
                          (float*)d_out, sections);
}

// round 6
// speedup vs baseline: 3.8483x; 2.3674x over previous
#include <cuda_runtime.h>
#include <cuda_fp16.h>
#include <cstdint>

#define BATCH 4096
#define INDIM 2048
#define HID   2048
#define KTOT  4096

#define BM 128
#define BN 128
#define BK 32
#define NSTG (KTOT / BK)                 // 128 k-chunks

#define ROWB 80                          // 64B data + 16B pad per row
#define TILE_BYTES (128 * ROWB)          // 10240
#define OFF_A 0
#define OFF_B TILE_BYTES
#define STAGE_BYTES (2 * TILE_BYTES)     // 20480
#define NPIPE 4
#define SMEM_BYTES (NPIPE * STAGE_BYTES) // 81920

#define DELTA    6e-3f
#define LIST_CAP (1u << 21)

// ---------------- device scratch ----------------
__device__ __half g_Ah[(size_t)BATCH * KTOT];    // [m][k]: fp16(X) | fp16(S)
__device__ __half g_Bh[(size_t)HID * KTOT];      // [n][k]: Wpsp^T | Wrec^T fp16
__device__ float  g_WfT[(size_t)HID * KTOT];     // [n][k]: exact fp32 W^T concat
__device__ uint32_t g_count;
__device__ uint32_t g_list[LIST_CAP];

// ---------------- helpers ----------------
__device__ __forceinline__ uint32_t s2u(const void* p) {
    uint32_t a;
    asm("{ .reg .u64 t; cvta.to.shared.u64 t, %1; cvt.u32.u64 %0, t; }"
        : "=r"(a) : "l"(p));
    return a;
}
__device__ __forceinline__ void cp16(uint32_t d, const void* s) {
    asm volatile("cp.async.cg.shared.global [%0], [%1], 16;" :: "r"(d), "l"(s));
}
__device__ __forceinline__ void ldm4(uint32_t* r, uint32_t addr) {
    asm volatile("ldmatrix.sync.aligned.m8n8.x4.shared.b16 {%0,%1,%2,%3}, [%4];"
                 : "=r"(r[0]), "=r"(r[1]), "=r"(r[2]), "=r"(r[3]) : "r"(addr));
}
__device__ __forceinline__ void mma16(float* d, const uint32_t* a, const uint32_t* b) {
    asm volatile(
        "mma.sync.aligned.m16n8k16.row.col.f32.f16.f16.f32 "
        "{%0,%1,%2,%3},{%4,%5,%6,%7},{%8,%9},{%0,%1,%2,%3};"
        : "+f"(d[0]), "+f"(d[1]), "+f"(d[2]), "+f"(d[3])
        : "r"(a[0]), "r"(a[1]), "r"(a[2]), "r"(a[3]), "r"(b[0]), "r"(b[1]));
}

// ---------------- pre-kernels ----------------
// Build A = [fp16(X) | fp16(S)] per row, and reset the fixup list.
__global__ void build_a_k(const float* __restrict__ X, const float* __restrict__ S) {
    size_t i = (size_t)blockIdx.x * blockDim.x + threadIdx.x;   // half2 index
    if (i == 0) g_count = 0;
    const size_t n2 = (size_t)BATCH * KTOT / 2;
    if (i >= n2) return;
    const int m = (int)(i >> 11);           // 2048 half2 per row
    const int c = (int)(i & 2047);
    const int k = c * 2;
    float2 v;
    if (k < INDIM) v = *(const float2*)(X + (size_t)m * INDIM + k);
    else           v = *(const float2*)(S + (size_t)m * HID + (k - INDIM));
    ((__half2*)g_Ah)[i] = __floats2half2_rn(v.x, v.y);
}
// Transpose W [k][n] -> B^T [n][k+off] in fp16 and fp32.
__global__ void trans_w_k(const float* __restrict__ W, int off) {
    __shared__ float tile[32][33];
    const int n0 = blockIdx.x * 32, k0 = blockIdx.y * 32;
    const int tx = threadIdx.x, ty = threadIdx.y;
    #pragma unroll
    for (int r = ty; r < 32; r += 8)
        tile[r][tx] = W[(size_t)(k0 + r) * HID + n0 + tx];
    __syncthreads();
    #pragma unroll
    for (int r = ty; r < 32; r += 8) {
        float v = tile[tx][r];                    // = W[k0+tx][n0+r]
        size_t o = (size_t)(n0 + r) * KTOT + off + k0 + tx;
        g_Bh[o]  = __float2half_rn(v);
        g_WfT[o] = v;
    }
}

// ---------------- main fused GEMM + LIF + band detect ----------------
__global__ void __launch_bounds__(256, 2)
gemm_lif(const float* __restrict__ S, const float* __restrict__ preC,
         const float* __restrict__ preV, const float* __restrict__ preTh,
         const float* __restrict__ mask, const float* __restrict__ bpsp,
         const float* __restrict__ brec, float* __restrict__ out, int sections)
{
    extern __shared__ char smem[];
    const uint32_t sb = s2u(smem);
    const int tid = threadIdx.x;
    const int lane = tid & 31, warp = tid >> 5;
    const int g = lane >> 2, t4 = lane & 3;
    const int wm = warp >> 2, wn = warp & 3;            // 2 x 4 warps, 64x32 tiles
    const int m0 = blockIdx.y * BM, n0 = blockIdx.x * BN;

    const uint32_t aoff = (uint32_t)((lane & 15) * ROWB + (lane >> 4) * 16);
    const uint32_t boff =
        (uint32_t)((((lane & 7) + ((lane >> 4) & 1) * 8)) * ROWB + ((lane >> 3) & 1) * 16);

    float acc[4][4][4];
    #pragma unroll
    for (int i = 0; i < 4; i++)
        #pragma unroll
        for (int j = 0; j < 4; j++)
            #pragma unroll
            for (int q = 0; q < 4; q++) acc[i][j][q] = 0.0f;

    // loader: 2 chunks of 16B per tile per thread
    auto load_stage = [&](int t) {
        const uint32_t base = sb + (uint32_t)((t & (NPIPE - 1)) * STAGE_BYTES);
        const int k0 = t * BK;
        #pragma unroll
        for (int i = 0; i < 2; i++) {
            const int u = tid + i * 256;
            const int r = u >> 2, c = u & 3;
            const uint32_t d = (uint32_t)(r * ROWB + c * 16);
            cp16(base + OFF_A + d, g_Ah + (size_t)(m0 + r) * KTOT + k0 + c * 8);
            cp16(base + OFF_B + d, g_Bh + (size_t)(n0 + r) * KTOT + k0 + c * 8);
        }
    };

    uint32_t fa[4][4], fb[4][2];
    auto compute_half = [&](uint32_t stb, int h) {
        const uint32_t kb = (uint32_t)(h * 32);
        #pragma unroll
        for (int mf = 0; mf < 4; mf++)
            ldm4(fa[mf], stb + OFF_A + (uint32_t)((wm * 64 + mf * 16) * ROWB) + kb + aoff);
        #pragma unroll
        for (int p = 0; p < 2; p++) {
            uint32_t r[4];
            ldm4(r, stb + OFF_B + (uint32_t)((wn * 32 + p * 16) * ROWB) + kb + boff);
            fb[2 * p][0] = r[0]; fb[2 * p][1] = r[1];
            fb[2 * p + 1][0] = r[2]; fb[2 * p + 1][1] = r[3];
        }
        #pragma unroll
        for (int mf = 0; mf < 4; mf++)
            #pragma unroll
            for (int nf = 0; nf < 4; nf++)
                mma16(acc[mf][nf], fa[mf], fb[nf]);
    };

    #pragma unroll
    for (int s = 0; s < NPIPE - 1; ++s) {
        load_stage(s);
        asm volatile("cp.async.commit_group;" ::: "memory");
    }

    for (int t = 0; t < NSTG; ++t) {
        asm volatile("cp.async.wait_group 2;" ::: "memory");
        __syncthreads();
        if (t + NPIPE - 1 < NSTG) load_stage(t + NPIPE - 1);
        asm volatile("cp.async.commit_group;" ::: "memory");

        const uint32_t stb = sb + (uint32_t)((t & (NPIPE - 1)) * STAGE_BYTES);
        compute_half(stb, 0);
        compute_half(stb, 1);
    }

    // ---------------- fused LIF epilogue + band detection ----------------
    const size_t NE = (size_t)BATCH * HID;
    #pragma unroll
    for (int mf = 0; mf < 4; mf++) {
        #pragma unroll
        for (int rh = 0; rh < 2; rh++) {
            const int m = m0 + wm * 64 + mf * 16 + g + rh * 8;
            const size_t row = (size_t)m * HID;
            #pragma unroll
            for (int nf = 0; nf < 4; nf++) {
                const int n = n0 + wn * 32 + nf * 8 + 2 * t4;
                const size_t idx = row + n;
                float2 pc = *(const float2*)(preC  + idx);
                float2 pv = *(const float2*)(preV  + idx);
                float2 ps = *(const float2*)(S     + idx);
                float2 pt = *(const float2*)(preTh + idx);
                float2 mk = *(const float2*)(mask  + idx);
                float2 b1 = *(const float2*)(bpsp  + n);
                float2 b2 = *(const float2*)(brec  + n);

                float av[2]  = { acc[mf][nf][rh * 2 + 0], acc[mf][nf][rh * 2 + 1] };
                float pcv[2] = { pc.x, pc.y }, pvv[2] = { pv.x, pv.y };
                float psv[2] = { ps.x, ps.y }, ptv[2] = { pt.x, pt.y };
                float mkv[2] = { mk.x, mk.y };
                float b1v[2] = { b1.x, b1.y }, b2v[2] = { b2.x, b2.y };

                float sp[2], cu[2], vo[2], th[2];
                #pragma unroll
                for (int q = 0; q < 2; q++) {
                    float c = fmaf(0.5f, pcv[q], av[q] + b1v[q] + b2v[q]);
                    c *= mkv[q];
                    float v = fmaf(0.75f * pvv[q], (1.0f - psv[q]), c);
                    float s = (v > ptv[q]) ? 1.0f : 0.0f;
                    float tv = (s != 0.0f) ? (ptv[q] + 0.05f)
                                           : fmaxf(ptv[q] * 0.9f, 1.0f);
                    sp[q] = s; cu[q] = c; vo[q] = v; th[q] = tv;
                    if (fabsf(v - ptv[q]) < DELTA) {
                        uint32_t pos = atomicAdd(&g_count, 1u);
                        if (pos < LIST_CAP)
                            g_list[pos] = (uint32_t)((m << 11) | (n + q));
                    }
                }
                *(float2*)(out + idx) = make_float2(sp[0], sp[1]);
                if (sections > 1) *(float2*)(out + NE + idx)     = make_float2(sp[0], sp[1]);
                if (sections > 2) *(float2*)(out + 2 * NE + idx) = make_float2(cu[0], cu[1]);
                if (sections > 3) *(float2*)(out + 3 * NE + idx) = make_float2(vo[0], vo[1]);
                if (sections > 4) *(float2*)(out + 4 * NE + idx) = make_float2(th[0], th[1]);
            }
        }
    }
}

// ---------------- exact fp32 fixup of near-threshold elements ----------------
__global__ void fixup_k(const float* __restrict__ X, const float* __restrict__ S,
                        const float* __restrict__ preC, const float* __restrict__ preV,
                        const float* __restrict__ preTh, const float* __restrict__ mask,
                        const float* __restrict__ bpsp, const float* __restrict__ brec,
                        float* __restrict__ out, int sections)
{
    const int lane = threadIdx.x & 31;
    const uint32_t wglob = (blockIdx.x * blockDim.x + threadIdx.x) >> 5;
    const uint32_t nw = (gridDim.x * blockDim.x) >> 5;
    uint32_t cnt = g_count;
    if (cnt > LIST_CAP) cnt = LIST_CAP;
    const size_t NE = (size_t)BATCH * HID;

    for (uint32_t i = wglob; i < cnt; i += nw) {
        const uint32_t e = g_list[i];
        const int m = (int)(e >> 11), n = (int)(e & 2047);
        const float* xr = X + (size_t)m * INDIM;
        const float* sr = S + (size_t)m * HID;
        const float* wr = g_WfT + (size_t)n * KTOT;          // [0:2048] psp
        const float* rr = g_WfT + (size_t)n * KTOT + INDIM;  // [2048:4096] rec
        float a = 0.0f;
        #pragma unroll 4
        for (int k = lane; k < INDIM; k += 32) a = fmaf(xr[k], wr[k], a);
        #pragma unroll 4
        for (int k = lane; k < HID; k += 32) a = fmaf(sr[k], rr[k], a);
        #pragma unroll
        for (int o = 16; o; o >>= 1) a += __shfl_xor_sync(0xFFFFFFFFu, a, o);

        if (lane == 0) {
            const size_t idx = (size_t)m * HID + n;
            float c = fmaf(0.5f, preC[idx], a + bpsp[n] + brec[n]);
            c *= mask[idx];
            float v = fmaf(0.75f * preV[idx], (1.0f - S[idx]), c);
            float pt = preTh[idx];
            float sp = (v > pt) ? 1.0f : 0.0f;
            float tv = (sp != 0.0f) ? (pt + 0.05f) : fmaxf(pt * 0.9f, 1.0f);
            out[idx] = sp;
            if (sections > 1) out[NE + idx]     = sp;
            if (sections > 2) out[2 * NE + idx] = c;
            if (sections > 3) out[3 * NE + idx] = v;
            if (sections > 4) out[4 * NE + idx] = tv;
        }
    }
}

// ---------------- launch ----------------
extern "C" void kernel_launch(void* const* d_in, const int* in_sizes, int n_in,
                              void* d_out, int out_size) {
    const float* X     = (const float*)d_in[0];
    const float* S     = (const float*)d_in[1];
    const float* preC  = (const float*)d_in[2];
    const float* preV  = (const float*)d_in[3];
    const float* preTh = (const float*)d_in[4];
    const float* mk    = (const float*)d_in[5];
    const float* Wpsp  = (const float*)d_in[6];
    const float* bpsp  = (const float*)d_in[7];
    const float* Wrec  = (const float*)d_in[8];
    const float* brec  = (const float*)d_in[9];

    const long long NE = (long long)BATCH * HID;
    int sections = (int)((long long)out_size / NE);
    if (sections < 1) sections = 1;
    if (sections > 5) sections = 5;

    cudaFuncSetAttribute(gemm_lif, cudaFuncAttributeMaxDynamicSharedMemorySize,
                         SMEM_BYTES);

    const size_t n2 = (size_t)BATCH * KTOT / 2;
    build_a_k<<<(unsigned)((n2 + 255) / 256), 256>>>(X, S);
    dim3 wg(HID / 32, INDIM / 32), wb(32, 8);
    trans_w_k<<<wg, wb>>>(Wpsp, 0);
    trans_w_k<<<wg, wb>>>(Wrec, INDIM);

    dim3 grid(HID / BN, BATCH / BM);   // (16, 32) = 512 CTAs
    gemm_lif<<<grid, 256, SMEM_BYTES>>>(S, preC, preV, preTh, mk, bpsp, brec,
                                        (float*)d_out, sections);
    fixup_k<<<256, 256>>>(X, S, preC, preV, preTh, mk, bpsp, brec,
                          (float*)d_out, sections);
}

// round 7
// speedup vs baseline: 3.8841x; 1.0093x over previous
#include <cuda_runtime.h>
#include <cuda_fp16.h>
#include <cstdint>

#define BATCH 4096
#define INDIM 2048
#define HID   2048
#define KTOT  4096

#define BM 128
#define BN 256
#define BK 32
#define NSTG (KTOT / BK)                  // 128 k-chunks

#define ROWB 80                           // 64B data + 16B pad
#define OFF_B (128 * ROWB)                // A tile: 128 rows
#define STAGE_BYTES (OFF_B + 256 * ROWB)  // + B tile: 256 rows = 30720
#define NPIPE 4
#define SMEM_BYTES (NPIPE * STAGE_BYTES)  // 122880

#define DELTA    3e-3f
#define LIST_CAP (1u << 21)

// ---------------- device scratch ----------------
__device__ __half g_Ah[(size_t)BATCH * KTOT];    // [m][k]: fp16(X) | fp16(S)
__device__ __half g_Bh[(size_t)HID * KTOT];      // [n][k]: Wpsp^T | Wrec^T fp16
__device__ float  g_WfT[(size_t)HID * KTOT];     // [n][k]: exact fp32 W^T concat
__device__ uint32_t g_count;
__device__ uint32_t g_list[LIST_CAP];

// ---------------- helpers ----------------
__device__ __forceinline__ uint32_t s2u(const void* p) {
    uint32_t a;
    asm("{ .reg .u64 t; cvta.to.shared.u64 t, %1; cvt.u32.u64 %0, t; }"
        : "=r"(a) : "l"(p));
    return a;
}
__device__ __forceinline__ void cp16(uint32_t d, const void* s) {
    asm volatile("cp.async.cg.shared.global [%0], [%1], 16;" :: "r"(d), "l"(s));
}
__device__ __forceinline__ void ldm4(uint32_t* r, uint32_t addr) {
    asm volatile("ldmatrix.sync.aligned.m8n8.x4.shared.b16 {%0,%1,%2,%3}, [%4];"
                 : "=r"(r[0]), "=r"(r[1]), "=r"(r[2]), "=r"(r[3]) : "r"(addr));
}
__device__ __forceinline__ void mma16(float* d, const uint32_t* a, const uint32_t* b) {
    asm volatile(
        "mma.sync.aligned.m16n8k16.row.col.f32.f16.f16.f32 "
        "{%0,%1,%2,%3},{%4,%5,%6,%7},{%8,%9},{%0,%1,%2,%3};"
        : "+f"(d[0]), "+f"(d[1]), "+f"(d[2]), "+f"(d[3])
        : "r"(a[0]), "r"(a[1]), "r"(a[2]), "r"(a[3]), "r"(b[0]), "r"(b[1]));
}

// ---------------- pre-kernels ----------------
__global__ void build_a_k(const float* __restrict__ X, const float* __restrict__ S) {
    size_t i = (size_t)blockIdx.x * blockDim.x + threadIdx.x;   // half2 index
    if (i == 0) g_count = 0;
    const size_t n2 = (size_t)BATCH * KTOT / 2;
    if (i >= n2) return;
    const int m = (int)(i >> 11);
    const int k = (int)(i & 2047) * 2;
    float2 v;
    if (k < INDIM) v = *(const float2*)(X + (size_t)m * INDIM + k);
    else           v = *(const float2*)(S + (size_t)m * HID + (k - INDIM));
    ((__half2*)g_Ah)[i] = __floats2half2_rn(v.x, v.y);
}
__global__ void trans_w_k(const float* __restrict__ Wpsp,
                          const float* __restrict__ Wrec) {
    __shared__ float tile[32][33];
    const float* W = blockIdx.z ? Wrec : Wpsp;
    const int off = blockIdx.z ? INDIM : 0;
    const int n0 = blockIdx.x * 32, k0 = blockIdx.y * 32;
    const int tx = threadIdx.x, ty = threadIdx.y;
    #pragma unroll
    for (int r = ty; r < 32; r += 8)
        tile[r][tx] = W[(size_t)(k0 + r) * HID + n0 + tx];
    __syncthreads();
    #pragma unroll
    for (int r = ty; r < 32; r += 8) {
        float v = tile[tx][r];                    // = W[k0+tx][n0+r]
        size_t o = (size_t)(n0 + r) * KTOT + off + k0 + tx;
        g_Bh[o]  = __float2half_rn(v);
        g_WfT[o] = v;
    }
}

// ---------------- main fused GEMM + LIF + band detect ----------------
__global__ void __launch_bounds__(256, 1)
gemm_lif(const float* __restrict__ S, const float* __restrict__ preC,
         const float* __restrict__ preV, const float* __restrict__ preTh,
         const float* __restrict__ mask, const float* __restrict__ bpsp,
         const float* __restrict__ brec, float* __restrict__ out, int sections)
{
    extern __shared__ char smem[];
    const uint32_t sb = s2u(smem);
    const int tid = threadIdx.x;
    const int lane = tid & 31, warp = tid >> 5;
    const int g = lane >> 2, t4 = lane & 3;
    const int wm = warp >> 2, wn = warp & 3;          // 2 x 4 warps, 64x64 tiles
    const int m0 = blockIdx.y * BM, n0 = blockIdx.x * BN;

    const uint32_t aoff = (uint32_t)((lane & 15) * ROWB + (lane >> 4) * 16);
    const uint32_t boff =
        (uint32_t)((((lane & 7) + ((lane >> 4) & 1) * 8)) * ROWB + ((lane >> 3) & 1) * 16);

    float acc[4][8][4];
    #pragma unroll
    for (int i = 0; i < 4; i++)
        #pragma unroll
        for (int j = 0; j < 8; j++)
            #pragma unroll
            for (int q = 0; q < 4; q++) acc[i][j][q] = 0.0f;

    // loader: A = 2 chunks, B = 4 chunks of 16B per thread
    auto load_stage = [&](int t) {
        const uint32_t base = sb + (uint32_t)((t & (NPIPE - 1)) * STAGE_BYTES);
        const int k0 = t * BK;
        #pragma unroll
        for (int i = 0; i < 2; i++) {
            const int u = tid + i * 256;
            const int r = u >> 2, c = u & 3;
            cp16(base + (uint32_t)(r * ROWB + c * 16),
                 g_Ah + (size_t)(m0 + r) * KTOT + k0 + c * 8);
        }
        #pragma unroll
        for (int i = 0; i < 4; i++) {
            const int u = tid + i * 256;
            const int r = u >> 2, c = u & 3;
            cp16(base + OFF_B + (uint32_t)(r * ROWB + c * 16),
                 g_Bh + (size_t)(n0 + r) * KTOT + k0 + c * 8);
        }
    };

    uint32_t fa[4][4], fb[8][2];
    auto compute_half = [&](uint32_t stb, int h) {
        const uint32_t kb = (uint32_t)(h * 32);
        #pragma unroll
        for (int mf = 0; mf < 4; mf++)
            ldm4(fa[mf], stb + (uint32_t)((wm * 64 + mf * 16) * ROWB) + kb + aoff);
        #pragma unroll
        for (int p = 0; p < 4; p++) {
            uint32_t r[4];
            ldm4(r, stb + OFF_B + (uint32_t)((wn * 64 + p * 16) * ROWB) + kb + boff);
            fb[2 * p][0] = r[0]; fb[2 * p][1] = r[1];
            fb[2 * p + 1][0] = r[2]; fb[2 * p + 1][1] = r[3];
        }
        #pragma unroll
        for (int mf = 0; mf < 4; mf++)
            #pragma unroll
            for (int nf = 0; nf < 8; nf++)
                mma16(acc[mf][nf], fa[mf], fb[nf]);
    };

    #pragma unroll
    for (int s = 0; s < NPIPE - 1; ++s) {
        load_stage(s);
        asm volatile("cp.async.commit_group;" ::: "memory");
    }

    for (int t = 0; t < NSTG; ++t) {
        asm volatile("cp.async.wait_group 2;" ::: "memory");
        __syncthreads();
        if (t + NPIPE - 1 < NSTG) load_stage(t + NPIPE - 1);
        asm volatile("cp.async.commit_group;" ::: "memory");

        const uint32_t stb = sb + (uint32_t)((t & (NPIPE - 1)) * STAGE_BYTES);
        compute_half(stb, 0);
        compute_half(stb, 1);
    }

    // ---------------- fused LIF epilogue + band detection ----------------
    const size_t NE = (size_t)BATCH * HID;
    #pragma unroll
    for (int mf = 0; mf < 4; mf++) {
        #pragma unroll
        for (int rh = 0; rh < 2; rh++) {
            const int m = m0 + wm * 64 + mf * 16 + g + rh * 8;
            const size_t row = (size_t)m * HID;
            #pragma unroll
            for (int nf = 0; nf < 8; nf++) {
                const int n = n0 + wn * 64 + nf * 8 + 2 * t4;
                const size_t idx = row + n;
                float2 pc = *(const float2*)(preC  + idx);
                float2 pv = *(const float2*)(preV  + idx);
                float2 ps = *(const float2*)(S     + idx);
                float2 pt = *(const float2*)(preTh + idx);
                float2 mk = *(const float2*)(mask  + idx);
                float2 b1 = *(const float2*)(bpsp  + n);
                float2 b2 = *(const float2*)(brec  + n);

                float av[2]  = { acc[mf][nf][rh * 2 + 0], acc[mf][nf][rh * 2 + 1] };
                float pcv[2] = { pc.x, pc.y }, pvv[2] = { pv.x, pv.y };
                float psv[2] = { ps.x, ps.y }, ptv[2] = { pt.x, pt.y };
                float mkv[2] = { mk.x, mk.y };
                float b1v[2] = { b1.x, b1.y }, b2v[2] = { b2.x, b2.y };

                float sp[2], cu[2], vo[2], th[2];
                #pragma unroll
                for (int q = 0; q < 2; q++) {
                    float c = fmaf(0.5f, pcv[q], av[q] + b1v[q] + b2v[q]);
                    c *= mkv[q];
                    float v = fmaf(0.75f * pvv[q], (1.0f - psv[q]), c);
                    float s = (v > ptv[q]) ? 1.0f : 0.0f;
                    float tv = (s != 0.0f) ? (ptv[q] + 0.05f)
                                           : fmaxf(ptv[q] * 0.9f, 1.0f);
                    sp[q] = s; cu[q] = c; vo[q] = v; th[q] = tv;

                    // warp-aggregated band-list append
                    const bool f = fabsf(v - ptv[q]) < DELTA;
                    const unsigned bal = __ballot_sync(0xFFFFFFFFu, f);
                    if (bal) {
                        const int leader = __ffs(bal) - 1;
                        uint32_t base = 0;
                        if (lane == leader)
                            base = atomicAdd(&g_count, (uint32_t)__popc(bal));
                        base = __shfl_sync(0xFFFFFFFFu, base, leader);
                        if (f) {
                            uint32_t pos = base + __popc(bal & ((1u << lane) - 1));
                            if (pos < LIST_CAP)
                                g_list[pos] = (uint32_t)((m << 11) | (n + q));
                        }
                    }
                }
                *(float2*)(out + idx) = make_float2(sp[0], sp[1]);
                if (sections > 1) *(float2*)(out + NE + idx)     = make_float2(sp[0], sp[1]);
                if (sections > 2) *(float2*)(out + 2 * NE + idx) = make_float2(cu[0], cu[1]);
                if (sections > 3) *(float2*)(out + 3 * NE + idx) = make_float2(vo[0], vo[1]);
                if (sections > 4) *(float2*)(out + 4 * NE + idx) = make_float2(th[0], th[1]);
            }
        }
    }
}

// ---------------- exact fp32 fixup of near-threshold elements ----------------
__global__ void fixup_k(const float* __restrict__ X, const float* __restrict__ S,
                        const float* __restrict__ preC, const float* __restrict__ preV,
                        const float* __restrict__ preTh, const float* __restrict__ mask,
                        const float* __restrict__ bpsp, const float* __restrict__ brec,
                        float* __restrict__ out, int sections)
{
    const int lane = threadIdx.x & 31;
    const uint32_t wglob = (blockIdx.x * blockDim.x + threadIdx.x) >> 5;
    const uint32_t nw = (gridDim.x * blockDim.x) >> 5;
    uint32_t cnt = g_count;
    if (cnt > LIST_CAP) cnt = LIST_CAP;
    const size_t NE = (size_t)BATCH * HID;

    for (uint32_t i = wglob; i < cnt; i += nw) {
        const uint32_t e = g_list[i];
        const int m = (int)(e >> 11), n = (int)(e & 2047);
        const float* xr = X + (size_t)m * INDIM;
        const float* sr = S + (size_t)m * HID;
        const float* wr = g_WfT + (size_t)n * KTOT;
        const float* rr = wr + INDIM;
        float a = 0.0f;
        #pragma unroll 4
        for (int k = lane; k < INDIM; k += 32) a = fmaf(xr[k], wr[k], a);
        #pragma unroll 4
        for (int k = lane; k < HID; k += 32) a = fmaf(sr[k], rr[k], a);
        #pragma unroll
        for (int o = 16; o; o >>= 1) a += __shfl_xor_sync(0xFFFFFFFFu, a, o);

        if (lane == 0) {
            const size_t idx = (size_t)m * HID + n;
            float c = fmaf(0.5f, preC[idx], a + bpsp[n] + brec[n]);
            c *= mask[idx];
            float v = fmaf(0.75f * preV[idx], (1.0f - S[idx]), c);
            float pt = preTh[idx];
            float sp = (v > pt) ? 1.0f : 0.0f;
            float tv = (sp != 0.0f) ? (pt + 0.05f) : fmaxf(pt * 0.9f, 1.0f);
            out[idx] = sp;
            if (sections > 1) out[NE + idx]     = sp;
            if (sections > 2) out[2 * NE + idx] = c;
            if (sections > 3) out[3 * NE + idx] = v;
            if (sections > 4) out[4 * NE + idx] = tv;
        }
    }
}

// ---------------- launch ----------------
extern "C" void kernel_launch(void* const* d_in, const int* in_sizes, int n_in,
                              void* d_out, int out_size) {
    const float* X     = (const float*)d_in[0];
    const float* S     = (const float*)d_in[1];
    const float* preC  = (const float*)d_in[2];
    const float* preV  = (const float*)d_in[3];
    const float* preTh = (const float*)d_in[4];
    const float* mk    = (const float*)d_in[5];
    const float* Wpsp  = (const float*)d_in[6];
    const float* bpsp  = (const float*)d_in[7];
    const float* Wrec  = (const float*)d_in[8];
    const float* brec  = (const float*)d_in[9];

    const long long NE = (long long)BATCH * HID;
    int sections = (int)((long long)out_size / NE);
    if (sections < 1) sections = 1;
    if (sections > 5) sections = 5;

    cudaFuncSetAttribute(gemm_lif, cudaFuncAttributeMaxDynamicSharedMemorySize,
                         SMEM_BYTES);

    const size_t n2 = (size_t)BATCH * KTOT / 2;
    build_a_k<<<(unsigned)((n2 + 255) / 256), 256>>>(X, S);
    dim3 wg(HID / 32, KTOT / 2 / 32, 2), wb(32, 8);
    trans_w_k<<<wg, wb>>>(Wpsp, Wrec);

    dim3 grid(HID / BN, BATCH / BM);   // (8, 32) = 256 CTAs
    gemm_lif<<<grid, 256, SMEM_BYTES>>>(S, preC, preV, preTh, mk, bpsp, brec,
                                        (float*)d_out, sections);
    fixup_k<<<512, 256>>>(X, S, preC, preV, preTh, mk, bpsp, brec,
                          (float*)d_out, sections);
}

// round 8
// speedup vs baseline: 5.0832x; 1.3087x over previous
#include <cuda_runtime.h>
#include <cuda_fp16.h>
#include <cstdint>

#define BATCH 4096
#define INDIM 2048
#define HID   2048
#define KTOT  4096

#define BM 128
#define BN 128
#define BK 32
#define NSTG (KTOT / BK)                 // 128 k-chunks

#define ROWB 80                          // 64B data + 16B pad per row
#define TILE_BYTES (128 * ROWB)          // 10240
#define OFF_A 0
#define OFF_B TILE_BYTES
#define STAGE_BYTES (2 * TILE_BYTES)     // 20480
#define NPIPE 4
#define SMEM_BYTES (NPIPE * STAGE_BYTES) // 81920

#define DELTA    3e-3f
#define LIST_CAP (1u << 21)

// ---------------- device scratch ----------------
__device__ __half g_Ah[(size_t)BATCH * KTOT];    // [m][k]: fp16(X) | fp16(S)
__device__ __half g_Bh[(size_t)HID * KTOT];      // [n][k]: Wpsp^T | Wrec^T fp16
__device__ float  g_WfT[(size_t)HID * KTOT];     // [n][k]: exact fp32 W^T concat
__device__ uint32_t g_count;
__device__ uint32_t g_list[LIST_CAP];

// ---------------- helpers ----------------
__device__ __forceinline__ uint32_t s2u(const void* p) {
    uint32_t a;
    asm("{ .reg .u64 t; cvta.to.shared.u64 t, %1; cvt.u32.u64 %0, t; }"
        : "=r"(a) : "l"(p));
    return a;
}
__device__ __forceinline__ void cp16(uint32_t d, const void* s) {
    asm volatile("cp.async.cg.shared.global [%0], [%1], 16;" :: "r"(d), "l"(s));
}
__device__ __forceinline__ void ldm4(uint32_t* r, uint32_t addr) {
    asm volatile("ldmatrix.sync.aligned.m8n8.x4.shared.b16 {%0,%1,%2,%3}, [%4];"
                 : "=r"(r[0]), "=r"(r[1]), "=r"(r[2]), "=r"(r[3]) : "r"(addr));
}
__device__ __forceinline__ void mma16(float* d, const uint32_t* a, const uint32_t* b) {
    asm volatile(
        "mma.sync.aligned.m16n8k16.row.col.f32.f16.f16.f32 "
        "{%0,%1,%2,%3},{%4,%5,%6,%7},{%8,%9},{%0,%1,%2,%3};"
        : "+f"(d[0]), "+f"(d[1]), "+f"(d[2]), "+f"(d[3])
        : "r"(a[0]), "r"(a[1]), "r"(a[2]), "r"(a[3]), "r"(b[0]), "r"(b[1]));
}

// ---------------- pre-kernels ----------------
__global__ void build_a_k(const float* __restrict__ X, const float* __restrict__ S) {
    size_t i = (size_t)blockIdx.x * blockDim.x + threadIdx.x;   // half2 index
    if (i == 0) g_count = 0;
    const size_t n2 = (size_t)BATCH * KTOT / 2;
    if (i >= n2) return;
    const int m = (int)(i >> 11);
    const int k = (int)(i & 2047) * 2;
    float2 v;
    if (k < INDIM) v = *(const float2*)(X + (size_t)m * INDIM + k);
    else           v = *(const float2*)(S + (size_t)m * HID + (k - INDIM));
    ((__half2*)g_Ah)[i] = __floats2half2_rn(v.x, v.y);
}
__global__ void trans_w_k(const float* __restrict__ Wpsp,
                          const float* __restrict__ Wrec) {
    __shared__ float tile[32][33];
    const float* W = blockIdx.z ? Wrec : Wpsp;
    const int off = blockIdx.z ? INDIM : 0;
    const int n0 = blockIdx.x * 32, k0 = blockIdx.y * 32;
    const int tx = threadIdx.x, ty = threadIdx.y;
    #pragma unroll
    for (int r = ty; r < 32; r += 8)
        tile[r][tx] = W[(size_t)(k0 + r) * HID + n0 + tx];
    __syncthreads();
    #pragma unroll
    for (int r = ty; r < 32; r += 8) {
        float v = tile[tx][r];                    // = W[k0+tx][n0+r]
        size_t o = (size_t)(n0 + r) * KTOT + off + k0 + tx;
        g_Bh[o]  = __float2half_rn(v);
        g_WfT[o] = v;
    }
}

// ---------------- main fused GEMM + LIF + band detect (R6 config) ----------------
__global__ void __launch_bounds__(256, 2)
gemm_lif(const float* __restrict__ S, const float* __restrict__ preC,
         const float* __restrict__ preV, const float* __restrict__ preTh,
         const float* __restrict__ mask, const float* __restrict__ bpsp,
         const float* __restrict__ brec, float* __restrict__ out, int sections)
{
    extern __shared__ char smem[];
    const uint32_t sb = s2u(smem);
    const int tid = threadIdx.x;
    const int lane = tid & 31, warp = tid >> 5;
    const int g = lane >> 2, t4 = lane & 3;
    const int wm = warp >> 2, wn = warp & 3;            // 2 x 4 warps, 64x32 tiles
    const int m0 = blockIdx.y * BM, n0 = blockIdx.x * BN;

    const uint32_t aoff = (uint32_t)((lane & 15) * ROWB + (lane >> 4) * 16);
    const uint32_t boff =
        (uint32_t)((((lane & 7) + ((lane >> 4) & 1) * 8)) * ROWB + ((lane >> 3) & 1) * 16);

    float acc[4][4][4];
    #pragma unroll
    for (int i = 0; i < 4; i++)
        #pragma unroll
        for (int j = 0; j < 4; j++)
            #pragma unroll
            for (int q = 0; q < 4; q++) acc[i][j][q] = 0.0f;

    auto load_stage = [&](int t) {
        const uint32_t base = sb + (uint32_t)((t & (NPIPE - 1)) * STAGE_BYTES);
        const int k0 = t * BK;
        #pragma unroll
        for (int i = 0; i < 2; i++) {
            const int u = tid + i * 256;
            const int r = u >> 2, c = u & 3;
            const uint32_t d = (uint32_t)(r * ROWB + c * 16);
            cp16(base + OFF_A + d, g_Ah + (size_t)(m0 + r) * KTOT + k0 + c * 8);
            cp16(base + OFF_B + d, g_Bh + (size_t)(n0 + r) * KTOT + k0 + c * 8);
        }
    };

    uint32_t fa[4][4], fb[4][2];
    auto compute_half = [&](uint32_t stb, int h) {
        const uint32_t kb = (uint32_t)(h * 32);
        #pragma unroll
        for (int mf = 0; mf < 4; mf++)
            ldm4(fa[mf], stb + OFF_A + (uint32_t)((wm * 64 + mf * 16) * ROWB) + kb + aoff);
        #pragma unroll
        for (int p = 0; p < 2; p++) {
            uint32_t r[4];
            ldm4(r, stb + OFF_B + (uint32_t)((wn * 32 + p * 16) * ROWB) + kb + boff);
            fb[2 * p][0] = r[0]; fb[2 * p][1] = r[1];
            fb[2 * p + 1][0] = r[2]; fb[2 * p + 1][1] = r[3];
        }
        #pragma unroll
        for (int mf = 0; mf < 4; mf++)
            #pragma unroll
            for (int nf = 0; nf < 4; nf++)
                mma16(acc[mf][nf], fa[mf], fb[nf]);
    };

    #pragma unroll
    for (int s = 0; s < NPIPE - 1; ++s) {
        load_stage(s);
        asm volatile("cp.async.commit_group;" ::: "memory");
    }

    for (int t = 0; t < NSTG; ++t) {
        asm volatile("cp.async.wait_group 2;" ::: "memory");
        __syncthreads();
        if (t + NPIPE - 1 < NSTG) load_stage(t + NPIPE - 1);
        asm volatile("cp.async.commit_group;" ::: "memory");

        const uint32_t stb = sb + (uint32_t)((t & (NPIPE - 1)) * STAGE_BYTES);
        compute_half(stb, 0);
        compute_half(stb, 1);
    }

    // ---------------- fused LIF epilogue + warp-aggregated band detect ----------------
    const size_t NE = (size_t)BATCH * HID;
    #pragma unroll
    for (int mf = 0; mf < 4; mf++) {
        #pragma unroll
        for (int rh = 0; rh < 2; rh++) {
            const int m = m0 + wm * 64 + mf * 16 + g + rh * 8;
            const size_t row = (size_t)m * HID;
            #pragma unroll
            for (int nf = 0; nf < 4; nf++) {
                const int n = n0 + wn * 32 + nf * 8 + 2 * t4;
                const size_t idx = row + n;
                float2 pc = *(const float2*)(preC  + idx);
                float2 pv = *(const float2*)(preV  + idx);
                float2 ps = *(const float2*)(S     + idx);
                float2 pt = *(const float2*)(preTh + idx);
                float2 mk = *(const float2*)(mask  + idx);
                float2 b1 = *(const float2*)(bpsp  + n);
                float2 b2 = *(const float2*)(brec  + n);

                float av[2]  = { acc[mf][nf][rh * 2 + 0], acc[mf][nf][rh * 2 + 1] };
                float pcv[2] = { pc.x, pc.y }, pvv[2] = { pv.x, pv.y };
                float psv[2] = { ps.x, ps.y }, ptv[2] = { pt.x, pt.y };
                float mkv[2] = { mk.x, mk.y };
                float b1v[2] = { b1.x, b1.y }, b2v[2] = { b2.x, b2.y };

                float sp[2], cu[2], vo[2], th[2];
                #pragma unroll
                for (int q = 0; q < 2; q++) {
                    float c = fmaf(0.5f, pcv[q], av[q] + b1v[q] + b2v[q]);
                    c *= mkv[q];
                    float v = fmaf(0.75f * pvv[q], (1.0f - psv[q]), c);
                    float s = (v > ptv[q]) ? 1.0f : 0.0f;
                    float tv = (s != 0.0f) ? (ptv[q] + 0.05f)
                                           : fmaxf(ptv[q] * 0.9f, 1.0f);
                    sp[q] = s; cu[q] = c; vo[q] = v; th[q] = tv;

                    const bool f = fabsf(v - ptv[q]) < DELTA;
                    const unsigned bal = __ballot_sync(0xFFFFFFFFu, f);
                    if (bal) {
                        const int leader = __ffs(bal) - 1;
                        uint32_t base = 0;
                        if (lane == leader)
                            base = atomicAdd(&g_count, (uint32_t)__popc(bal));
                        base = __shfl_sync(0xFFFFFFFFu, base, leader);
                        if (f) {
                            uint32_t pos = base + __popc(bal & ((1u << lane) - 1));
                            if (pos < LIST_CAP)
                                g_list[pos] = (uint32_t)((m << 11) | (n + q));
                        }
                    }
                }
                *(float2*)(out + idx) = make_float2(sp[0], sp[1]);
                if (sections > 1) *(float2*)(out + NE + idx)     = make_float2(sp[0], sp[1]);
                if (sections > 2) *(float2*)(out + 2 * NE + idx) = make_float2(cu[0], cu[1]);
                if (sections > 3) *(float2*)(out + 3 * NE + idx) = make_float2(vo[0], vo[1]);
                if (sections > 4) *(float2*)(out + 4 * NE + idx) = make_float2(th[0], th[1]);
            }
        }
    }
}

// ---------------- exact fp32 fixup (vectorized float4 loads) ----------------
__global__ void fixup_k(const float* __restrict__ X, const float* __restrict__ S,
                        const float* __restrict__ preC, const float* __restrict__ preV,
                        const float* __restrict__ preTh, const float* __restrict__ mask,
                        const float* __restrict__ bpsp, const float* __restrict__ brec,
                        float* __restrict__ out, int sections)
{
    const int lane = threadIdx.x & 31;
    const uint32_t wglob = (blockIdx.x * blockDim.x + threadIdx.x) >> 5;
    const uint32_t nw = (gridDim.x * blockDim.x) >> 5;
    uint32_t cnt = g_count;
    if (cnt > LIST_CAP) cnt = LIST_CAP;
    const size_t NE = (size_t)BATCH * HID;

    for (uint32_t i = wglob; i < cnt; i += nw) {
        const uint32_t e = g_list[i];
        const int m = (int)(e >> 11), n = (int)(e & 2047);
        const float4* xr = (const float4*)(X + (size_t)m * INDIM);
        const float4* sr = (const float4*)(S + (size_t)m * HID);
        const float4* wr = (const float4*)(g_WfT + (size_t)n * KTOT);
        const float4* rr = (const float4*)(g_WfT + (size_t)n * KTOT + INDIM);
        float a = 0.0f;
        #pragma unroll 4
        for (int k = lane; k < INDIM / 4; k += 32) {
            float4 x = xr[k], w = wr[k];
            a = fmaf(x.x, w.x, a); a = fmaf(x.y, w.y, a);
            a = fmaf(x.z, w.z, a); a = fmaf(x.w, w.w, a);
        }
        #pragma unroll 4
        for (int k = lane; k < HID / 4; k += 32) {
            float4 x = sr[k], w = rr[k];
            a = fmaf(x.x, w.x, a); a = fmaf(x.y, w.y, a);
            a = fmaf(x.z, w.z, a); a = fmaf(x.w, w.w, a);
        }
        #pragma unroll
        for (int o = 16; o; o >>= 1) a += __shfl_xor_sync(0xFFFFFFFFu, a, o);

        if (lane == 0) {
            const size_t idx = (size_t)m * HID + n;
            float c = fmaf(0.5f, preC[idx], a + bpsp[n] + brec[n]);
            c *= mask[idx];
            float v = fmaf(0.75f * preV[idx], (1.0f - S[idx]), c);
            float pt = preTh[idx];
            float sp = (v > pt) ? 1.0f : 0.0f;
            float tv = (sp != 0.0f) ? (pt + 0.05f) : fmaxf(pt * 0.9f, 1.0f);
            out[idx] = sp;
            if (sections > 1) out[NE + idx]     = sp;
            if (sections > 2) out[2 * NE + idx] = c;
            if (sections > 3) out[3 * NE + idx] = v;
            if (sections > 4) out[4 * NE + idx] = tv;
        }
    }
}

// ---------------- launch ----------------
extern "C" void kernel_launch(void* const* d_in, const int* in_sizes, int n_in,
                              void* d_out, int out_size) {
    const float* X     = (const float*)d_in[0];
    const float* S     = (const float*)d_in[1];
    const float* preC  = (const float*)d_in[2];
    const float* preV  = (const float*)d_in[3];
    const float* preTh = (const float*)d_in[4];
    const float* mk    = (const float*)d_in[5];
    const float* Wpsp  = (const float*)d_in[6];
    const float* bpsp  = (const float*)d_in[7];
    const float* Wrec  = (const float*)d_in[8];
    const float* brec  = (const float*)d_in[9];

    const long long NE = (long long)BATCH * HID;
    int sections = (int)((long long)out_size / NE);
    if (sections < 1) sections = 1;
    if (sections > 5) sections = 5;

    cudaFuncSetAttribute(gemm_lif, cudaFuncAttributeMaxDynamicSharedMemorySize,
                         SMEM_BYTES);

    const size_t n2 = (size_t)BATCH * KTOT / 2;
    build_a_k<<<(unsigned)((n2 + 255) / 256), 256>>>(X, S);
    dim3 wg(HID / 32, KTOT / 2 / 32, 2), wb(32, 8);
    trans_w_k<<<wg, wb>>>(Wpsp, Wrec);

    dim3 grid(HID / BN, BATCH / BM);   // (16, 32) = 512 CTAs
    gemm_lif<<<grid, 256, SMEM_BYTES>>>(S, preC, preV, preTh, mk, bpsp, brec,
                                        (float*)d_out, sections);
    fixup_k<<<512, 256>>>(X, S, preC, preV, preTh, mk, bpsp, brec,
                          (float*)d_out, sections);
}